// round 12
// baseline (speedup 1.0000x reference)
#include <cuda_runtime.h>
#include <cuda_bf16.h>
#include <math.h>
#include <stdint.h>

#define BATCH 2
#define C     192
#define S     32768
#define NH    8
#define DH    64
#define INNER 512
#define ATT_SCALE 0.125f
#define GC    64
#define SPB   (S / GC)      // 512
#define WSZ   98304
#define XTOT  ((size_t)BATCH * C * S)

// ---------------- device scratch ----------------
__device__ __nv_bfloat16 g_Xh[(size_t)BATCH * C * S];
__device__ __nv_bfloat16 g_Xl[(size_t)BATCH * C * S];
__device__ __nv_bfloat16 g_Wh[4 * WSZ];
__device__ __nv_bfloat16 g_Wl[4 * WSZ];
__device__ float g_Gpart[BATCH * GC * 6 * 64 * 64];
__device__ __nv_bfloat16 g_Gh[BATCH * C * C];
__device__ __nv_bfloat16 g_Gl[BATCH * C * C];
__device__ float g_simp[BATCH * NH * 3 * 64 * 64];
__device__ __nv_bfloat16 g_AVh[BATCH * INNER * C];
__device__ __nv_bfloat16 g_AVl[BATCH * INNER * C];
__device__ __nv_bfloat16 g_Mh[BATCH * C * C];
__device__ __nv_bfloat16 g_Ml[BATCH * C * C];

__constant__ int c_ti[6] = {0, 64, 128, 0,  0,   64};
__constant__ int c_tj[6] = {0, 64, 128, 64, 128, 128};

// ---------------- helpers ----------------
__device__ __forceinline__ uint32_t s2u(const void* p) {
    return (uint32_t)__cvta_generic_to_shared(p);
}

__device__ __forceinline__ void cp16(uint32_t s, const void* g) {
    asm volatile("cp.async.cg.shared.global [%0], [%1], 16;\n" :: "r"(s), "l"(g));
}
#define CP_COMMIT() asm volatile("cp.async.commit_group;\n" ::: "memory")
#define CP_WAIT1()  asm volatile("cp.async.wait_group 1;\n" ::: "memory")
#define CP_WAIT0()  asm volatile("cp.async.wait_group 0;\n" ::: "memory")

#define LDSM4(R0,R1,R2,R3,ADDR) \
    asm volatile("ldmatrix.sync.aligned.m8n8.x4.shared.b16 {%0,%1,%2,%3}, [%4];" \
        : "=r"(R0),"=r"(R1),"=r"(R2),"=r"(R3) : "r"(ADDR))

#define LDSM4T(R0,R1,R2,R3,ADDR) \
    asm volatile("ldmatrix.sync.aligned.m8n8.x4.trans.shared.b16 {%0,%1,%2,%3}, [%4];" \
        : "=r"(R0),"=r"(R1),"=r"(R2),"=r"(R3) : "r"(ADDR))

__device__ __forceinline__ void mma2(float c[4], uint32_t a0, uint32_t a1, uint32_t a2, uint32_t a3,
                                     uint32_t b0, uint32_t b1) {
    asm volatile(
        "mma.sync.aligned.m16n8k16.row.col.f32.bf16.bf16.f32 "
        "{%0,%1,%2,%3}, {%4,%5,%6,%7}, {%8,%9}, {%0,%1,%2,%3};\n"
        : "+f"(c[0]), "+f"(c[1]), "+f"(c[2]), "+f"(c[3])
        : "r"(a0), "r"(a1), "r"(a2), "r"(a3), "r"(b0), "r"(b1));
}

__device__ __forceinline__ void split_pack(float x0, float x1, uint32_t& hi, uint32_t& lo) {
    __nv_bfloat16 h0 = __float2bfloat16_rn(x0);
    __nv_bfloat16 h1 = __float2bfloat16_rn(x1);
    __nv_bfloat16 l0 = __float2bfloat16_rn(x0 - __bfloat162float(h0));
    __nv_bfloat16 l1 = __float2bfloat16_rn(x1 - __bfloat162float(h1));
    __nv_bfloat162 hp; hp.x = h0; hp.y = h1;
    __nv_bfloat162 lp; lp.x = l0; lp.y = l1;
    hi = *reinterpret_cast<uint32_t*>(&hp);
    lo = *reinterpret_cast<uint32_t*>(&lp);
}

// ============ K0: X + weights -> bf16 hi/lo planes ============
__global__ void __launch_bounds__(256) k_cvt(const float* __restrict__ x,
                                             const float* __restrict__ wq,
                                             const float* __restrict__ wk,
                                             const float* __restrict__ wv,
                                             const float* __restrict__ wo) {
    size_t i8 = ((size_t)blockIdx.x * 256 + threadIdx.x) * 8;
    const float* src;
    __nv_bfloat16 *dsth, *dstl;
    size_t off;
    if (i8 < XTOT) {
        src = x; off = i8; dsth = g_Xh + i8; dstl = g_Xl + i8;
    } else {
        size_t wi = i8 - XTOT;
        int w = (int)(wi / WSZ);
        off = wi % WSZ;
        src = (w == 0) ? wq : (w == 1) ? wk : (w == 2) ? wv : wo;
        dsth = g_Wh + wi; dstl = g_Wl + wi;
    }
    float4 v0 = *reinterpret_cast<const float4*>(src + off);
    float4 v1 = *reinterpret_cast<const float4*>(src + off + 4);
    uint32_t h0, h1, h2, h3, l0, l1, l2, l3;
    split_pack(v0.x, v0.y, h0, l0);
    split_pack(v0.z, v0.w, h1, l1);
    split_pack(v1.x, v1.y, h2, l2);
    split_pack(v1.z, v1.w, h3, l3);
    *reinterpret_cast<uint4*>(dsth) = make_uint4(h0, h1, h2, h3);
    *reinterpret_cast<uint4*>(dstl) = make_uint4(l0, l1, l2, l3);
}

// ============ K1: gram partials (cp.async 3-stage + ldmatrix) ============
#define GPAD 72
#define G_SPLIT_OFF (64 * GPAD)
#define G_A_BYTES   (2 * 64 * GPAD * 2)
#define G_STAGE     (2 * G_A_BYTES)
#define G_SMEM      (3 * G_STAGE)
#define G_ITERS     (SPB / 64)            // 8

__global__ void __launch_bounds__(256, 2) k_gram() {
    extern __shared__ char dyn[];
    int tile  = blockIdx.x;
    int chunk = blockIdx.y;
    int b     = blockIdx.z;
    int i0 = c_ti[tile], j0 = c_tj[tile];
    bool diag = (i0 == j0);
    const __nv_bfloat16* xh = g_Xh + (size_t)b * C * S;
    const __nv_bfloat16* xl = g_Xl + (size_t)b * C * S;

    int tid  = threadIdx.x;
    int w    = tid >> 5, lane = tid & 31;
    int grp  = lane >> 2, tig = lane & 3;
    int wm   = w & 1, wn = w >> 1;
    int rsel = lane & 15, csel = (lane >> 4) << 3;

    float acc[2][2][4] = {};
    int sbeg = chunk * SPB;
    int crow = tid >> 2, cs16 = (tid & 3) * 16;

    auto issue = [&](int st, int sb) {
        uint32_t base = s2u(dyn + st * G_STAGE);
        const __nv_bfloat16* ghA = xh + (size_t)(i0 + crow) * S + sb + cs16;
        const __nv_bfloat16* glA = xl + (size_t)(i0 + crow) * S + sb + cs16;
        uint32_t sa = base + 2 * (crow * GPAD + cs16);
        cp16(sa, ghA);
        cp16(sa + 16, ghA + 8);
        cp16(sa + 2 * G_SPLIT_OFF, glA);
        cp16(sa + 2 * G_SPLIT_OFF + 16, glA + 8);
        if (!diag) {
            const __nv_bfloat16* ghB = xh + (size_t)(j0 + crow) * S + sb + cs16;
            const __nv_bfloat16* glB = xl + (size_t)(j0 + crow) * S + sb + cs16;
            uint32_t sb2 = base + G_A_BYTES + 2 * (crow * GPAD + cs16);
            cp16(sb2, ghB);
            cp16(sb2 + 16, ghB + 8);
            cp16(sb2 + 2 * G_SPLIT_OFF, glB);
            cp16(sb2 + 2 * G_SPLIT_OFF + 16, glB + 8);
        }
        CP_COMMIT();
    };

    issue(0, sbeg);
    issue(1, sbeg + 64);

    for (int it = 0; it < G_ITERS; it++) {
        if (it + 1 < G_ITERS) { CP_WAIT1(); } else { CP_WAIT0(); }
        __syncthreads();   // all warps past own WAIT -> stage it%3 full; also all finished iter it-1

        if (it + 2 < G_ITERS) issue((it + 2) % 3, sbeg + (it + 2) * 64);

        uint32_t sAu = s2u(dyn + (it % 3) * G_STAGE);
        uint32_t sBu = diag ? sAu : (sAu + G_A_BYTES);
        #pragma unroll
        for (int ks = 0; ks < 4; ks++) {
            int kb = ks * 16;
            uint32_t a[2][2][4];
            #pragma unroll
            for (int h = 0; h < 2; h++)
                #pragma unroll
                for (int mf = 0; mf < 2; mf++) {
                    uint32_t addr = sAu + 2 * (h * G_SPLIT_OFF + (wm * 32 + mf * 16 + rsel) * GPAD + kb + csel);
                    LDSM4(a[h][mf][0], a[h][mf][1], a[h][mf][2], a[h][mf][3], addr);
                }
            uint32_t bm[2][4];
            #pragma unroll
            for (int h = 0; h < 2; h++) {
                uint32_t addr = sBu + 2 * (h * G_SPLIT_OFF + (wn * 16 + rsel) * GPAD + kb + csel);
                LDSM4(bm[h][0], bm[h][1], bm[h][2], bm[h][3], addr);
            }
            #pragma unroll
            for (int mf = 0; mf < 2; mf++)
                #pragma unroll
                for (int nf = 0; nf < 2; nf++) {
                    mma2(acc[mf][nf], a[0][mf][0], a[0][mf][1], a[0][mf][2], a[0][mf][3], bm[0][nf], bm[0][nf + 2]);
                    mma2(acc[mf][nf], a[0][mf][0], a[0][mf][1], a[0][mf][2], a[0][mf][3], bm[1][nf], bm[1][nf + 2]);
                    mma2(acc[mf][nf], a[1][mf][0], a[1][mf][1], a[1][mf][2], a[1][mf][3], bm[0][nf], bm[0][nf + 2]);
                }
        }
        // no trailing sync: next iteration's post-WAIT sync provides the ordering
    }

    float* Gp = g_Gpart + ((size_t)((b * GC + chunk) * 6 + tile)) * 4096;
    #pragma unroll
    for (int mf = 0; mf < 2; mf++)
        #pragma unroll
        for (int nf = 0; nf < 2; nf++) {
            int row = wm * 32 + mf * 16 + grp;
            int col = wn * 16 + nf * 8 + tig * 2;
            *reinterpret_cast<float2*>(&Gp[row * 64 + col])       = make_float2(acc[mf][nf][0], acc[mf][nf][1]);
            *reinterpret_cast<float2*>(&Gp[(row + 8) * 64 + col]) = make_float2(acc[mf][nf][2], acc[mf][nf][3]);
        }
}

// reduce -> bf16 hi/lo planes of G (symmetric fill); grid (6, 4, BATCH), float4 loads
__global__ void k_gram_reduce() {
    int tile = blockIdx.x, seg = blockIdx.y, b = blockIdx.z;
    int i0 = c_ti[tile], j0 = c_tj[tile];
    __nv_bfloat16* Gh = g_Gh + (size_t)b * C * C;
    __nv_bfloat16* Gl = g_Gl + (size_t)b * C * C;
    int e4 = seg * 1024 + threadIdx.x * 4;
    float4 s = make_float4(0.f, 0.f, 0.f, 0.f);
    #pragma unroll 8
    for (int ch = 0; ch < GC; ch++) {
        float4 v = *reinterpret_cast<const float4*>(
            &g_Gpart[((size_t)((b * GC + ch) * 6 + tile)) * 4096 + e4]);
        s.x += v.x; s.y += v.y; s.z += v.z; s.w += v.w;
    }
    float vs[4] = {s.x, s.y, s.z, s.w};
    #pragma unroll
    for (int u = 0; u < 4; u++) {
        int e = e4 + u;
        __nv_bfloat16 h = __float2bfloat16_rn(vs[u]);
        __nv_bfloat16 l = __float2bfloat16_rn(vs[u] - __bfloat162float(h));
        int m = e >> 6, n = e & 63;
        Gh[(i0 + m) * C + j0 + n] = h;
        Gl[(i0 + m) * C + j0 + n] = l;
        Gh[(j0 + n) * C + i0 + m] = h;
        Gl[(j0 + n) * C + i0 + m] = l;
    }
}

// ============ K2: fused (Wq@G)->T->sim partial, mma. grid (3 dc, NH, BATCH) ============
#define QPAD 200
#define TPAD 72
#define Q_WQ_H 0
#define Q_WQ_L (64 * QPAD)
#define Q_G_H  (2 * 64 * QPAD)
#define Q_G_L  (3 * 64 * QPAD)
#define Q_WK_H (4 * 64 * QPAD)
#define Q_WK_L (Q_WK_H + 64 * TPAD)
#define Q_T_H  (Q_WK_H + 2 * 64 * TPAD)
#define Q_T_L  (Q_WK_H + 3 * 64 * TPAD)
#define QG_SMEM ((4 * 64 * QPAD + 4 * 64 * TPAD) * 2)

__global__ void __launch_bounds__(256, 1) k_qgsim() {
    extern __shared__ __nv_bfloat16 sb[];
    int dc = blockIdx.x, n = blockIdx.y, b = blockIdx.z;
    int tid = threadIdx.x;
    int w    = tid >> 5, lane = tid & 31;
    int grp  = lane >> 2, tig = lane & 3;
    int wm   = w & 1, wn = w >> 1;
    int rsel = lane & 15, csel = (lane >> 4) << 3;

    int lrow = tid >> 2, lc = tid & 3;

    // group 1: Wq + G (needed for phase 1)
    {
        const __nv_bfloat16* wqh = g_Wh + (size_t)(n * 64 + lrow) * C + lc * 48;
        const __nv_bfloat16* wql = g_Wl + (size_t)(n * 64 + lrow) * C + lc * 48;
        const __nv_bfloat16* gh  = g_Gh + (size_t)b * C * C + (size_t)(dc * 64 + lrow) * C + lc * 48;
        const __nv_bfloat16* gl  = g_Gl + (size_t)b * C * C + (size_t)(dc * 64 + lrow) * C + lc * 48;
        uint32_t dq_h = s2u(&sb[Q_WQ_H + lrow * QPAD + lc * 48]);
        uint32_t dq_l = s2u(&sb[Q_WQ_L + lrow * QPAD + lc * 48]);
        uint32_t dg_h = s2u(&sb[Q_G_H + lrow * QPAD + lc * 48]);
        uint32_t dg_l = s2u(&sb[Q_G_L + lrow * QPAD + lc * 48]);
        #pragma unroll
        for (int j = 0; j < 6; j++) {
            cp16(dq_h + j * 16, wqh + j * 8);
            cp16(dq_l + j * 16, wql + j * 8);
            cp16(dg_h + j * 16, gh + j * 8);
            cp16(dg_l + j * 16, gl + j * 8);
        }
        CP_COMMIT();
    }
    // group 2: Wk (only needed for phase 2 -> hidden behind phase 1)
    {
        const __nv_bfloat16* wkh = g_Wh + WSZ + (size_t)(n * 64 + lrow) * C + dc * 64 + lc * 16;
        const __nv_bfloat16* wkl = g_Wl + WSZ + (size_t)(n * 64 + lrow) * C + dc * 64 + lc * 16;
        uint32_t dk_h = s2u(&sb[Q_WK_H + lrow * TPAD + lc * 16]);
        uint32_t dk_l = s2u(&sb[Q_WK_L + lrow * TPAD + lc * 16]);
        #pragma unroll
        for (int j = 0; j < 2; j++) {
            cp16(dk_h + j * 16, wkh + j * 8);
            cp16(dk_l + j * 16, wkl + j * 8);
        }
        CP_COMMIT();
    }
    CP_WAIT1();
    __syncthreads();

    uint32_t base = s2u(sb);
    float acc[2][2][4] = {};
    #pragma unroll
    for (int ks = 0; ks < 12; ks++) {
        int kb = ks * 16;
        uint32_t a[2][2][4];
        #pragma unroll
        for (int h = 0; h < 2; h++)
            #pragma unroll
            for (int mf = 0; mf < 2; mf++) {
                uint32_t addr = base + 2 * ((h ? Q_WQ_L : Q_WQ_H) + (wm * 32 + mf * 16 + rsel) * QPAD + kb + csel);
                LDSM4(a[h][mf][0], a[h][mf][1], a[h][mf][2], a[h][mf][3], addr);
            }
        uint32_t bm[2][4];
        #pragma unroll
        for (int h = 0; h < 2; h++) {
            uint32_t addr = base + 2 * ((h ? Q_G_L : Q_G_H) + (wn * 16 + rsel) * QPAD + kb + csel);
            LDSM4(bm[h][0], bm[h][1], bm[h][2], bm[h][3], addr);
        }
        #pragma unroll
        for (int mf = 0; mf < 2; mf++)
            #pragma unroll
            for (int nf = 0; nf < 2; nf++) {
                mma2(acc[mf][nf], a[0][mf][0], a[0][mf][1], a[0][mf][2], a[0][mf][3], bm[0][nf], bm[0][nf + 2]);
                mma2(acc[mf][nf], a[0][mf][0], a[0][mf][1], a[0][mf][2], a[0][mf][3], bm[1][nf], bm[1][nf + 2]);
                mma2(acc[mf][nf], a[1][mf][0], a[1][mf][1], a[1][mf][2], a[1][mf][3], bm[0][nf], bm[0][nf + 2]);
            }
    }

    #pragma unroll
    for (int mf = 0; mf < 2; mf++)
        #pragma unroll
        for (int nf = 0; nf < 2; nf++) {
            int row = wm * 32 + mf * 16 + grp;
            int col = wn * 16 + nf * 8 + tig * 2;
            uint32_t hi, lo;
            split_pack(acc[mf][nf][0], acc[mf][nf][1], hi, lo);
            *reinterpret_cast<uint32_t*>(&sb[Q_T_H + row * TPAD + col]) = hi;
            *reinterpret_cast<uint32_t*>(&sb[Q_T_L + row * TPAD + col]) = lo;
            split_pack(acc[mf][nf][2], acc[mf][nf][3], hi, lo);
            *reinterpret_cast<uint32_t*>(&sb[Q_T_H + (row + 8) * TPAD + col]) = hi;
            *reinterpret_cast<uint32_t*>(&sb[Q_T_L + (row + 8) * TPAD + col]) = lo;
        }
    CP_WAIT0();   // own Wk group done; barrier makes all warps' Wk visible
    __syncthreads();

    float sacc[2][2][4] = {};
    #pragma unroll
    for (int ks = 0; ks < 4; ks++) {
        int kb = ks * 16;
        uint32_t a[2][2][4];
        #pragma unroll
        for (int h = 0; h < 2; h++)
            #pragma unroll
            for (int mf = 0; mf < 2; mf++) {
                uint32_t addr = base + 2 * ((h ? Q_T_L : Q_T_H) + (wm * 32 + mf * 16 + rsel) * TPAD + kb + csel);
                LDSM4(a[h][mf][0], a[h][mf][1], a[h][mf][2], a[h][mf][3], addr);
            }
        uint32_t bm[2][4];
        #pragma unroll
        for (int h = 0; h < 2; h++) {
            uint32_t addr = base + 2 * ((h ? Q_WK_L : Q_WK_H) + (wn * 16 + rsel) * TPAD + kb + csel);
            LDSM4(bm[h][0], bm[h][1], bm[h][2], bm[h][3], addr);
        }
        #pragma unroll
        for (int mf = 0; mf < 2; mf++)
            #pragma unroll
            for (int nf = 0; nf < 2; nf++) {
                mma2(sacc[mf][nf], a[0][mf][0], a[0][mf][1], a[0][mf][2], a[0][mf][3], bm[0][nf], bm[0][nf + 2]);
                mma2(sacc[mf][nf], a[0][mf][0], a[0][mf][1], a[0][mf][2], a[0][mf][3], bm[1][nf], bm[1][nf + 2]);
                mma2(sacc[mf][nf], a[1][mf][0], a[1][mf][1], a[1][mf][2], a[1][mf][3], bm[0][nf], bm[0][nf + 2]);
            }
    }

    float* sp = g_simp + (((size_t)(b * NH + n)) * 3 + dc) * 4096;
    #pragma unroll
    for (int mf = 0; mf < 2; mf++)
        #pragma unroll
        for (int nf = 0; nf < 2; nf++) {
            int row = wm * 32 + mf * 16 + grp;
            int col = wn * 16 + nf * 8 + tig * 2;
            *reinterpret_cast<float2*>(&sp[row * 64 + col])       = make_float2(sacc[mf][nf][0], sacc[mf][nf][1]);
            *reinterpret_cast<float2*>(&sp[(row + 8) * 64 + col]) = make_float2(sacc[mf][nf][2], sacc[mf][nf][3]);
        }
}

// ============ K3: fused softmax + AV (mma). grid (3 c-tiles, NH, BATCH) ============
#define AV_P_F    (3 * 64 * 68)
#define AV_BF_OFF ((AV_P_F + 64 * 65) * 4)
#define AV_A_H 0
#define AV_A_L (64 * TPAD)
#define AV_V_H (2 * 64 * TPAD)
#define AV_V_L (3 * 64 * TPAD)
#define AV_SMEM (AV_BF_OFF + 4 * 64 * TPAD * 2)

__global__ void __launch_bounds__(256, 1) k_av2() {
    extern __shared__ float sf[];
    float* sP   = sf;
    float* sims = sf + AV_P_F;
    __nv_bfloat16* sbm = reinterpret_cast<__nv_bfloat16*>(reinterpret_cast<char*>(sf) + AV_BF_OFF);

    int c0 = blockIdx.x * 64;
    int n  = blockIdx.y;
    int b  = blockIdx.z;

    int tid = threadIdx.x;
    int w    = tid >> 5, lane = tid & 31;
    int grp  = lane >> 2, tig = lane & 3;
    int wm   = w & 1, wn = w >> 1;
    int rsel = lane & 15, csel = (lane >> 4) << 3;

    int lrow = tid >> 2, lc = tid & 3;

    const float* p = g_simp + ((size_t)(b * NH + n)) * 3 * 4096;
    #pragma unroll
    for (int pp = 0; pp < 3; pp++) {
        const float* gp = p + pp * 4096 + lrow * 64 + lc * 16;
        uint32_t spu = s2u(&sP[pp * 64 * 68 + lrow * 68 + lc * 16]);
        #pragma unroll
        for (int j = 0; j < 4; j++)
            cp16(spu + j * 16, gp + j * 4);
    }
    {
        const __nv_bfloat16* gvh = g_Wh + 2 * WSZ + (size_t)(n * 64 + lrow) * C + c0 + lc * 16;
        const __nv_bfloat16* gvl = g_Wl + 2 * WSZ + (size_t)(n * 64 + lrow) * C + c0 + lc * 16;
        uint32_t dvh = s2u(&sbm[AV_V_H + lrow * TPAD + lc * 16]);
        uint32_t dvl = s2u(&sbm[AV_V_L + lrow * TPAD + lc * 16]);
        #pragma unroll
        for (int j = 0; j < 2; j++) {
            cp16(dvh + j * 16, gvh + j * 8);
            cp16(dvl + j * 16, gvl + j * 8);
        }
    }
    CP_COMMIT();
    CP_WAIT0();
    __syncthreads();

    for (int e = tid; e < 4096; e += 256) {
        int r = e >> 6, q = e & 63;
        sims[r * 65 + q] = (sP[r * 68 + q] + sP[64 * 68 + r * 68 + q] + sP[2 * 64 * 68 + r * 68 + q]) * ATT_SCALE;
    }
    __syncthreads();

    for (int r = w; r < 64; r += 8) {
        float v0 = sims[r * 65 + lane], v1 = sims[r * 65 + lane + 32];
        float m = fmaxf(v0, v1);
        #pragma unroll
        for (int off = 16; off; off >>= 1)
            m = fmaxf(m, __shfl_xor_sync(0xffffffffu, m, off));
        float e0 = __expf(v0 - m);
        float e1 = __expf(v1 - m);
        float sum = e0 + e1;
        #pragma unroll
        for (int off = 16; off; off >>= 1)
            sum += __shfl_xor_sync(0xffffffffu, sum, off);
        float inv = 1.f / sum;
        sims[r * 65 + lane]      = e0 * inv;
        sims[r * 65 + lane + 32] = e1 * inv;
    }
    __syncthreads();

    {
        int row = tid >> 2, q0 = (tid & 3) * 16;
        #pragma unroll
        for (int j2 = 0; j2 < 8; j2++) {
            uint32_t hi, lo;
            split_pack(sims[row * 65 + q0 + 2 * j2], sims[row * 65 + q0 + 2 * j2 + 1], hi, lo);
            *reinterpret_cast<uint32_t*>(&sbm[AV_A_H + row * TPAD + q0 + 2 * j2]) = hi;
            *reinterpret_cast<uint32_t*>(&sbm[AV_A_L + row * TPAD + q0 + 2 * j2]) = lo;
        }
    }
    __syncthreads();

    uint32_t base = s2u(sbm);
    float acc[2][2][4] = {};
    #pragma unroll
    for (int ks = 0; ks < 4; ks++) {
        int kb = ks * 16;
        uint32_t a[2][2][4];
        #pragma unroll
        for (int h = 0; h < 2; h++)
            #pragma unroll
            for (int mf = 0; mf < 2; mf++) {
                uint32_t addr = base + 2 * ((h ? AV_A_L : AV_A_H) + (wm * 32 + mf * 16 + rsel) * TPAD + kb + csel);
                LDSM4(a[h][mf][0], a[h][mf][1], a[h][mf][2], a[h][mf][3], addr);
            }
        uint32_t bm[2][2][2];
        #pragma unroll
        for (int h = 0; h < 2; h++) {
            uint32_t addr = base + 2 * ((h ? AV_V_L : AV_V_H) + (kb + rsel) * TPAD + wn * 16 + csel);
            uint32_t r0, r1, r2, r3;
            LDSM4T(r0, r1, r2, r3, addr);
            bm[h][0][0] = r0; bm[h][0][1] = r1;
            bm[h][1][0] = r2; bm[h][1][1] = r3;
        }
        #pragma unroll
        for (int mf = 0; mf < 2; mf++)
            #pragma unroll
            for (int nf = 0; nf < 2; nf++) {
                mma2(acc[mf][nf], a[0][mf][0], a[0][mf][1], a[0][mf][2], a[0][mf][3], bm[0][nf][0], bm[0][nf][1]);
                mma2(acc[mf][nf], a[0][mf][0], a[0][mf][1], a[0][mf][2], a[0][mf][3], bm[1][nf][0], bm[1][nf][1]);
                mma2(acc[mf][nf], a[1][mf][0], a[1][mf][1], a[1][mf][2], a[1][mf][3], bm[0][nf][0], bm[0][nf][1]);
            }
    }

    #pragma unroll
    for (int mf = 0; mf < 2; mf++)
        #pragma unroll
        for (int nf = 0; nf < 2; nf++) {
            int row = wm * 32 + mf * 16 + grp;
            int col = c0 + wn * 16 + nf * 8 + tig * 2;
            size_t base0 = ((size_t)b * INNER + n * 64 + row) * C + col;
            size_t base8 = ((size_t)b * INNER + n * 64 + row + 8) * C + col;
            uint32_t hi, lo;
            split_pack(acc[mf][nf][0], acc[mf][nf][1], hi, lo);
            *reinterpret_cast<uint32_t*>(&g_AVh[base0]) = hi;
            *reinterpret_cast<uint32_t*>(&g_AVl[base0]) = lo;
            split_pack(acc[mf][nf][2], acc[mf][nf][3], hi, lo);
            *reinterpret_cast<uint32_t*>(&g_AVh[base8]) = hi;
            *reinterpret_cast<uint32_t*>(&g_AVl[base8]) = lo;
        }
}

// ============ K4: M = Wo @ AV (mma, full K=512, 3-stage pipeline). grid (3, 3, BATCH) ============
#define WOPAD 136
#define M_WO_H 0
#define M_WO_L (64 * WOPAD)
#define M_AV_H (2 * 64 * WOPAD)
#define M_AV_L (M_AV_H + 128 * TPAD)
#define M_STAGE ((2 * 64 * WOPAD + 2 * 128 * TPAD) * 2)   // 71680
#define M_SMEM  (3 * M_STAGE)                              // 215040
#define M_ITERS 4

__global__ void __launch_bounds__(256, 1) k_m() {
    extern __shared__ char dyn[];
    int c0 = blockIdx.x * 64;
    int o0 = blockIdx.y * 64;
    int b  = blockIdx.z;

    int tid = threadIdx.x;
    int w    = tid >> 5, lane = tid & 31;
    int grp  = lane >> 2, tig = lane & 3;
    int wm   = w & 1, wn = w >> 1;
    int rsel = lane & 15, csel = (lane >> 4) << 3;

    int lrow = tid >> 2, lcw = (tid & 3) * 32;
    int arow = tid >> 1, ac = (tid & 1) * 32;

    auto issue = [&](int st, int k0) {
        __nv_bfloat16* sb = (__nv_bfloat16*)(dyn + st * M_STAGE);
        const __nv_bfloat16* gwh = g_Wh + 3 * WSZ + (size_t)(o0 + lrow) * INNER + k0 + lcw;
        const __nv_bfloat16* gwl = g_Wl + 3 * WSZ + (size_t)(o0 + lrow) * INNER + k0 + lcw;
        uint32_t dwh = s2u(&sb[M_WO_H + lrow * WOPAD + lcw]);
        uint32_t dwl = s2u(&sb[M_WO_L + lrow * WOPAD + lcw]);
        #pragma unroll
        for (int j = 0; j < 4; j++) {
            cp16(dwh + j * 16, gwh + j * 8);
            cp16(dwl + j * 16, gwl + j * 8);
        }
        const __nv_bfloat16* gah = g_AVh + ((size_t)b * INNER + k0 + arow) * C + c0 + ac;
        const __nv_bfloat16* gal = g_AVl + ((size_t)b * INNER + k0 + arow) * C + c0 + ac;
        uint32_t dah = s2u(&sb[M_AV_H + arow * TPAD + ac]);
        uint32_t dal = s2u(&sb[M_AV_L + arow * TPAD + ac]);
        #pragma unroll
        for (int j = 0; j < 4; j++) {
            cp16(dah + j * 16, gah + j * 8);
            cp16(dal + j * 16, gal + j * 8);
        }
        CP_COMMIT();
    };

    issue(0, 0);
    issue(1, 128);

    float acc[2][2][4] = {};
    for (int it = 0; it < M_ITERS; it++) {
        if (it + 1 < M_ITERS) { CP_WAIT1(); } else { CP_WAIT0(); }
        __syncthreads();

        if (it + 2 < M_ITERS) issue((it + 2) % 3, (it + 2) * 128);

        uint32_t base = s2u(dyn + (it % 3) * M_STAGE);
        #pragma unroll
        for (int ks = 0; ks < 8; ks++) {
            int kb = ks * 16;
            uint32_t a[2][2][4];
            #pragma unroll
            for (int h = 0; h < 2; h++)
                #pragma unroll
                for (int mf = 0; mf < 2; mf++) {
                    uint32_t addr = base + 2 * ((h ? M_WO_L : M_WO_H) + (wm * 32 + mf * 16 + rsel) * WOPAD + kb + csel);
                    LDSM4(a[h][mf][0], a[h][mf][1], a[h][mf][2], a[h][mf][3], addr);
                }
            uint32_t bm[2][2][2];
            #pragma unroll
            for (int h = 0; h < 2; h++) {
                uint32_t addr = base + 2 * ((h ? M_AV_L : M_AV_H) + (kb + rsel) * TPAD + wn * 16 + csel);
                uint32_t r0, r1, r2, r3;
                LDSM4T(r0, r1, r2, r3, addr);
                bm[h][0][0] = r0; bm[h][0][1] = r1;
                bm[h][1][0] = r2; bm[h][1][1] = r3;
            }
            #pragma unroll
            for (int mf = 0; mf < 2; mf++)
                #pragma unroll
                for (int nf = 0; nf < 2; nf++) {
                    mma2(acc[mf][nf], a[0][mf][0], a[0][mf][1], a[0][mf][2], a[0][mf][3], bm[0][nf][0], bm[0][nf][1]);
                    mma2(acc[mf][nf], a[0][mf][0], a[0][mf][1], a[0][mf][2], a[0][mf][3], bm[1][nf][0], bm[1][nf][1]);
                    mma2(acc[mf][nf], a[1][mf][0], a[1][mf][1], a[1][mf][2], a[1][mf][3], bm[0][nf][0], bm[0][nf][1]);
                }
        }
    }

    __nv_bfloat16* Mh = g_Mh + (size_t)b * C * C;
    __nv_bfloat16* Ml = g_Ml + (size_t)b * C * C;
    #pragma unroll
    for (int mf = 0; mf < 2; mf++)
        #pragma unroll
        for (int nf = 0; nf < 2; nf++) {
            int row = o0 + wm * 32 + mf * 16 + grp;
            int col = c0 + wn * 16 + nf * 8 + tig * 2;
            uint32_t hi, lo;
            split_pack(acc[mf][nf][0], acc[mf][nf][1], hi, lo);
            *reinterpret_cast<uint32_t*>(&Mh[row * C + col]) = hi;
            *reinterpret_cast<uint32_t*>(&Ml[row * C + col]) = lo;
            split_pack(acc[mf][nf][2], acc[mf][nf][3], hi, lo);
            *reinterpret_cast<uint32_t*>(&Mh[(row + 8) * C + col]) = hi;
            *reinterpret_cast<uint32_t*>(&Ml[(row + 8) * C + col]) = lo;
        }
}

// ============ K5: out = M @ X + bo (cp.async 3-stage + ldmatrix) ============
#define MPAD 40
#define SPAD 136
#define O_M_BYTES     (2 * 64 * MPAD * 2)
#define O_X_BYTES     (2 * 32 * SPAD * 2)
#define O_M_SPLIT_OFF (64 * MPAD)
#define O_X_SPLIT_OFF (32 * SPAD)
#define O_STAGE       (O_M_BYTES + O_X_BYTES)
#define O_SMEM        (3 * O_STAGE)
#define O_ITERS       6

__global__ void __launch_bounds__(256, 2) k_out(const float* __restrict__ bo,
                                                float* __restrict__ out) {
    extern __shared__ char dyn[];
    int o0    = blockIdx.x * 64;
    int s0blk = blockIdx.y * 128;
    int b     = blockIdx.z;

    int tid  = threadIdx.x;
    int w    = tid >> 5, lane = tid & 31;
    int grp  = lane >> 2, tig = lane & 3;
    int wm   = w & 1, wn = w >> 1;
    int rsel = lane & 15, csel = (lane >> 4) << 3;

    const __nv_bfloat16* xh = g_Xh + (size_t)b * C * S;
    const __nv_bfloat16* xl = g_Xl + (size_t)b * C * S;
    const __nv_bfloat16* mh = g_Mh + (size_t)b * C * C;
    const __nv_bfloat16* ml = g_Ml + (size_t)b * C * C;

    float acc[2][4][4] = {};

    int mrow = tid >> 2, mk8 = (tid & 3) * 8;
    int krow = tid >> 3, s16o = (tid & 7) * 16;

    auto issue = [&](int st, int kc) {
        uint32_t mb  = s2u(dyn + st * O_STAGE);
        uint32_t xbs = mb + O_M_BYTES;
        const __nv_bfloat16* gmh = mh + (o0 + mrow) * C + kc + mk8;
        const __nv_bfloat16* gml = ml + (o0 + mrow) * C + kc + mk8;
        uint32_t sm = mb + 2 * (mrow * MPAD + mk8);
        cp16(sm, gmh);
        cp16(sm + 2 * O_M_SPLIT_OFF, gml);
        const __nv_bfloat16* gxh = xh + (size_t)(kc + krow) * S + s0blk + s16o;
        const __nv_bfloat16* gxl = xl + (size_t)(kc + krow) * S + s0blk + s16o;
        uint32_t sx = xbs + 2 * (krow * SPAD + s16o);
        cp16(sx, gxh);
        cp16(sx + 16, gxh + 8);
        cp16(sx + 2 * O_X_SPLIT_OFF, gxl);
        cp16(sx + 2 * O_X_SPLIT_OFF + 16, gxl + 8);
        CP_COMMIT();
    };

    issue(0, 0);
    issue(1, 32);

    for (int it = 0; it < O_ITERS; it++) {
        if (it + 1 < O_ITERS) { CP_WAIT1(); } else { CP_WAIT0(); }
        __syncthreads();

        if (it + 2 < O_ITERS) issue((it + 2) % 3, (it + 2) * 32);

        uint32_t sMu = s2u(dyn + (it % 3) * O_STAGE);
        uint32_t sXu = sMu + O_M_BYTES;
        #pragma unroll
        for (int ks = 0; ks < 2; ks++) {
            int kb = ks * 16;
            uint32_t a[2][2][4];
            #pragma unroll
            for (int h = 0; h < 2; h++)
                #pragma unroll
                for (int mf = 0; mf < 2; mf++) {
                    uint32_t addr = sMu + 2 * (h * O_M_SPLIT_OFF + (wm * 32 + mf * 16 + rsel) * MPAD + kb + csel);
                    LDSM4(a[h][mf][0], a[h][mf][1], a[h][mf][2], a[h][mf][3], addr);
                }
            uint32_t bb[2][4][2];
            #pragma unroll
            for (int h = 0; h < 2; h++)
                #pragma unroll
                for (int nfp = 0; nfp < 2; nfp++) {
                    int scol = wn * 32 + nfp * 16;
                    uint32_t addr = sXu + 2 * (h * O_X_SPLIT_OFF + (kb + rsel) * SPAD + scol + csel);
                    uint32_t r0, r1, r2, r3;
                    LDSM4T(r0, r1, r2, r3, addr);
                    bb[h][nfp * 2][0] = r0; bb[h][nfp * 2][1] = r1;
                    bb[h][nfp * 2 + 1][0] = r2; bb[h][nfp * 2 + 1][1] = r3;
                }
            #pragma unroll
            for (int mf = 0; mf < 2; mf++)
                #pragma unroll
                for (int nf = 0; nf < 4; nf++) {
                    mma2(acc[mf][nf], a[0][mf][0], a[0][mf][1], a[0][mf][2], a[0][mf][3], bb[0][nf][0], bb[0][nf][1]);
                    mma2(acc[mf][nf], a[0][mf][0], a[0][mf][1], a[0][mf][2], a[0][mf][3], bb[1][nf][0], bb[1][nf][1]);
                    mma2(acc[mf][nf], a[1][mf][0], a[1][mf][1], a[1][mf][2], a[1][mf][3], bb[0][nf][0], bb[0][nf][1]);
                }
        }
        // no trailing sync: next iteration's post-WAIT sync provides the ordering
    }

    #pragma unroll
    for (int mf = 0; mf < 2; mf++) {
        int row0 = o0 + wm * 32 + mf * 16 + grp;
        float bias0 = bo[row0];
        float bias1 = bo[row0 + 8];
        #pragma unroll
        for (int nf = 0; nf < 4; nf++) {
            int col = s0blk + wn * 32 + nf * 8 + tig * 2;
            *reinterpret_cast<float2*>(&out[((size_t)b * C + row0) * S + col]) =
                make_float2(acc[mf][nf][0] + bias0, acc[mf][nf][1] + bias0);
            *reinterpret_cast<float2*>(&out[((size_t)b * C + row0 + 8) * S + col]) =
                make_float2(acc[mf][nf][2] + bias1, acc[mf][nf][3] + bias1);
        }
    }
}

// ---------------- launch ----------------
extern "C" void kernel_launch(void* const* d_in, const int* in_sizes, int n_in,
                              void* d_out, int out_size) {
    const float* x  = (const float*)d_in[0];
    const float* wq = (const float*)d_in[1];
    const float* wk = (const float*)d_in[2];
    const float* wv = (const float*)d_in[3];
    const float* wo = (const float*)d_in[4];
    const float* bo = (const float*)d_in[5];
    float* out = (float*)d_out;

    cudaFuncSetAttribute(k_gram,  cudaFuncAttributeMaxDynamicSharedMemorySize, G_SMEM);
    cudaFuncSetAttribute(k_qgsim, cudaFuncAttributeMaxDynamicSharedMemorySize, QG_SMEM);
    cudaFuncSetAttribute(k_av2,   cudaFuncAttributeMaxDynamicSharedMemorySize, AV_SMEM);
    cudaFuncSetAttribute(k_m,     cudaFuncAttributeMaxDynamicSharedMemorySize, M_SMEM);
    cudaFuncSetAttribute(k_out,   cudaFuncAttributeMaxDynamicSharedMemorySize, O_SMEM);

    int cvt_blocks = (int)((XTOT + 4 * WSZ) / (256 * 8));
    k_cvt<<<cvt_blocks, 256>>>(x, wq, wk, wv, wo);
    k_gram<<<dim3(6, GC, BATCH), 256, G_SMEM>>>();
    k_gram_reduce<<<dim3(6, 4, BATCH), 256>>>();
    k_qgsim<<<dim3(3, NH, BATCH), 256, QG_SMEM>>>();
    k_av2<<<dim3(3, NH, BATCH), 256, AV_SMEM>>>();
    k_m<<<dim3(3, 3, BATCH), 256, M_SMEM>>>();
    k_out<<<dim3(3, S / 128, BATCH), 256, O_SMEM>>>(bo, out);
}

// round 13
// speedup vs baseline: 1.0386x; 1.0386x over previous
#include <cuda_runtime.h>
#include <cuda_bf16.h>
#include <math.h>
#include <stdint.h>

#define BATCH 2
#define C     192
#define S     32768
#define NH    8
#define DH    64
#define INNER 512
#define ATT_SCALE 0.125f
#define GC    32
#define SPB   (S / GC)      // 1024
#define WSZ   98304
#define XTOT  ((size_t)BATCH * C * S)

// ---------------- device scratch ----------------
__device__ __nv_bfloat16 g_Xh[(size_t)BATCH * C * S];
__device__ __nv_bfloat16 g_Xl[(size_t)BATCH * C * S];
__device__ __nv_bfloat16 g_Wh[4 * WSZ];
__device__ __nv_bfloat16 g_Wl[4 * WSZ];
__device__ float g_Gpart[BATCH * GC * 6 * 64 * 64];
__device__ __nv_bfloat16 g_Gh[BATCH * C * C];
__device__ __nv_bfloat16 g_Gl[BATCH * C * C];
__device__ float g_simp[BATCH * NH * 3 * 64 * 64];
__device__ __nv_bfloat16 g_AVh[BATCH * INNER * C];
__device__ __nv_bfloat16 g_AVl[BATCH * INNER * C];
__device__ float g_Mpart[BATCH * 4 * C * C];
__device__ __nv_bfloat16 g_Mh[BATCH * C * C];
__device__ __nv_bfloat16 g_Ml[BATCH * C * C];

__constant__ int c_ti[6] = {0, 64, 128, 0,  0,   64};
__constant__ int c_tj[6] = {0, 64, 128, 64, 128, 128};

// ---------------- helpers ----------------
__device__ __forceinline__ uint32_t s2u(const void* p) {
    return (uint32_t)__cvta_generic_to_shared(p);
}

__device__ __forceinline__ void cp16(uint32_t s, const void* g) {
    asm volatile("cp.async.cg.shared.global [%0], [%1], 16;\n" :: "r"(s), "l"(g));
}
#define CP_COMMIT() asm volatile("cp.async.commit_group;\n" ::: "memory")
#define CP_WAIT1()  asm volatile("cp.async.wait_group 1;\n" ::: "memory")
#define CP_WAIT0()  asm volatile("cp.async.wait_group 0;\n" ::: "memory")

#define LDSM4(R0,R1,R2,R3,ADDR) \
    asm volatile("ldmatrix.sync.aligned.m8n8.x4.shared.b16 {%0,%1,%2,%3}, [%4];" \
        : "=r"(R0),"=r"(R1),"=r"(R2),"=r"(R3) : "r"(ADDR))

#define LDSM4T(R0,R1,R2,R3,ADDR) \
    asm volatile("ldmatrix.sync.aligned.m8n8.x4.trans.shared.b16 {%0,%1,%2,%3}, [%4];" \
        : "=r"(R0),"=r"(R1),"=r"(R2),"=r"(R3) : "r"(ADDR))

__device__ __forceinline__ void mma2(float c[4], uint32_t a0, uint32_t a1, uint32_t a2, uint32_t a3,
                                     uint32_t b0, uint32_t b1) {
    asm volatile(
        "mma.sync.aligned.m16n8k16.row.col.f32.bf16.bf16.f32 "
        "{%0,%1,%2,%3}, {%4,%5,%6,%7}, {%8,%9}, {%0,%1,%2,%3};\n"
        : "+f"(c[0]), "+f"(c[1]), "+f"(c[2]), "+f"(c[3])
        : "r"(a0), "r"(a1), "r"(a2), "r"(a3), "r"(b0), "r"(b1));
}

__device__ __forceinline__ void split_pack(float x0, float x1, uint32_t& hi, uint32_t& lo) {
    __nv_bfloat16 h0 = __float2bfloat16_rn(x0);
    __nv_bfloat16 h1 = __float2bfloat16_rn(x1);
    __nv_bfloat16 l0 = __float2bfloat16_rn(x0 - __bfloat162float(h0));
    __nv_bfloat16 l1 = __float2bfloat16_rn(x1 - __bfloat162float(h1));
    __nv_bfloat162 hp; hp.x = h0; hp.y = h1;
    __nv_bfloat162 lp; lp.x = l0; lp.y = l1;
    hi = *reinterpret_cast<uint32_t*>(&hp);
    lo = *reinterpret_cast<uint32_t*>(&lp);
}

// ============ K0: X + weights -> bf16 hi/lo planes ============
__global__ void __launch_bounds__(256) k_cvt(const float* __restrict__ x,
                                             const float* __restrict__ wq,
                                             const float* __restrict__ wk,
                                             const float* __restrict__ wv,
                                             const float* __restrict__ wo) {
    size_t i8 = ((size_t)blockIdx.x * 256 + threadIdx.x) * 8;
    const float* src;
    __nv_bfloat16 *dsth, *dstl;
    size_t off;
    if (i8 < XTOT) {
        src = x; off = i8; dsth = g_Xh + i8; dstl = g_Xl + i8;
    } else {
        size_t wi = i8 - XTOT;
        int w = (int)(wi / WSZ);
        off = wi % WSZ;
        src = (w == 0) ? wq : (w == 1) ? wk : (w == 2) ? wv : wo;
        dsth = g_Wh + wi; dstl = g_Wl + wi;
    }
    float4 v0 = *reinterpret_cast<const float4*>(src + off);
    float4 v1 = *reinterpret_cast<const float4*>(src + off + 4);
    uint32_t h0, h1, h2, h3, l0, l1, l2, l3;
    split_pack(v0.x, v0.y, h0, l0);
    split_pack(v0.z, v0.w, h1, l1);
    split_pack(v1.x, v1.y, h2, l2);
    split_pack(v1.z, v1.w, h3, l3);
    *reinterpret_cast<uint4*>(dsth) = make_uint4(h0, h1, h2, h3);
    *reinterpret_cast<uint4*>(dstl) = make_uint4(l0, l1, l2, l3);
}

// ============ K1: gram partials (cp.async 3-stage + ldmatrix) ============
#define GPAD 72
#define G_SPLIT_OFF (64 * GPAD)
#define G_A_BYTES   (2 * 64 * GPAD * 2)
#define G_STAGE     (2 * G_A_BYTES)
#define G_SMEM      (3 * G_STAGE)
#define G_ITERS     (SPB / 64)            // 16

__global__ void __launch_bounds__(256, 2) k_gram() {
    extern __shared__ char dyn[];
    int tile  = blockIdx.x;
    int chunk = blockIdx.y;
    int b     = blockIdx.z;
    int i0 = c_ti[tile], j0 = c_tj[tile];
    bool diag = (i0 == j0);
    const __nv_bfloat16* xh = g_Xh + (size_t)b * C * S;
    const __nv_bfloat16* xl = g_Xl + (size_t)b * C * S;

    int tid  = threadIdx.x;
    int w    = tid >> 5, lane = tid & 31;
    int grp  = lane >> 2, tig = lane & 3;
    int wm   = w & 1, wn = w >> 1;
    int rsel = lane & 15, csel = (lane >> 4) << 3;

    float acc[2][2][4] = {};
    int sbeg = chunk * SPB;
    int crow = tid >> 2, cs16 = (tid & 3) * 16;

    auto issue = [&](int st, int sb) {
        uint32_t base = s2u(dyn + st * G_STAGE);
        const __nv_bfloat16* ghA = xh + (size_t)(i0 + crow) * S + sb + cs16;
        const __nv_bfloat16* glA = xl + (size_t)(i0 + crow) * S + sb + cs16;
        uint32_t sa = base + 2 * (crow * GPAD + cs16);
        cp16(sa, ghA);
        cp16(sa + 16, ghA + 8);
        cp16(sa + 2 * G_SPLIT_OFF, glA);
        cp16(sa + 2 * G_SPLIT_OFF + 16, glA + 8);
        if (!diag) {
            const __nv_bfloat16* ghB = xh + (size_t)(j0 + crow) * S + sb + cs16;
            const __nv_bfloat16* glB = xl + (size_t)(j0 + crow) * S + sb + cs16;
            uint32_t sb2 = base + G_A_BYTES + 2 * (crow * GPAD + cs16);
            cp16(sb2, ghB);
            cp16(sb2 + 16, ghB + 8);
            cp16(sb2 + 2 * G_SPLIT_OFF, glB);
            cp16(sb2 + 2 * G_SPLIT_OFF + 16, glB + 8);
        }
        CP_COMMIT();
    };

    issue(0, sbeg);
    issue(1, sbeg + 64);

    for (int it = 0; it < G_ITERS; it++) {
        if (it + 1 < G_ITERS) { CP_WAIT1(); } else { CP_WAIT0(); }
        __syncthreads();   // single barrier per iter: orders prev-iter reads + own stage full

        if (it + 2 < G_ITERS) issue((it + 2) % 3, sbeg + (it + 2) * 64);

        uint32_t sAu = s2u(dyn + (it % 3) * G_STAGE);
        uint32_t sBu = diag ? sAu : (sAu + G_A_BYTES);
        #pragma unroll
        for (int ks = 0; ks < 4; ks++) {
            int kb = ks * 16;
            uint32_t a[2][2][4];
            #pragma unroll
            for (int h = 0; h < 2; h++)
                #pragma unroll
                for (int mf = 0; mf < 2; mf++) {
                    uint32_t addr = sAu + 2 * (h * G_SPLIT_OFF + (wm * 32 + mf * 16 + rsel) * GPAD + kb + csel);
                    LDSM4(a[h][mf][0], a[h][mf][1], a[h][mf][2], a[h][mf][3], addr);
                }
            uint32_t bm[2][4];
            #pragma unroll
            for (int h = 0; h < 2; h++) {
                uint32_t addr = sBu + 2 * (h * G_SPLIT_OFF + (wn * 16 + rsel) * GPAD + kb + csel);
                LDSM4(bm[h][0], bm[h][1], bm[h][2], bm[h][3], addr);
            }
            #pragma unroll
            for (int mf = 0; mf < 2; mf++)
                #pragma unroll
                for (int nf = 0; nf < 2; nf++) {
                    mma2(acc[mf][nf], a[0][mf][0], a[0][mf][1], a[0][mf][2], a[0][mf][3], bm[0][nf], bm[0][nf + 2]);
                    mma2(acc[mf][nf], a[0][mf][0], a[0][mf][1], a[0][mf][2], a[0][mf][3], bm[1][nf], bm[1][nf + 2]);
                    mma2(acc[mf][nf], a[1][mf][0], a[1][mf][1], a[1][mf][2], a[1][mf][3], bm[0][nf], bm[0][nf + 2]);
                }
        }
    }

    float* Gp = g_Gpart + ((size_t)((b * GC + chunk) * 6 + tile)) * 4096;
    #pragma unroll
    for (int mf = 0; mf < 2; mf++)
        #pragma unroll
        for (int nf = 0; nf < 2; nf++) {
            int row = wm * 32 + mf * 16 + grp;
            int col = wn * 16 + nf * 8 + tig * 2;
            *reinterpret_cast<float2*>(&Gp[row * 64 + col])       = make_float2(acc[mf][nf][0], acc[mf][nf][1]);
            *reinterpret_cast<float2*>(&Gp[(row + 8) * 64 + col]) = make_float2(acc[mf][nf][2], acc[mf][nf][3]);
        }
}

// reduce -> bf16 hi/lo planes of G (symmetric fill); grid (6, 4, BATCH), float4 loads
__global__ void k_gram_reduce() {
    int tile = blockIdx.x, seg = blockIdx.y, b = blockIdx.z;
    int i0 = c_ti[tile], j0 = c_tj[tile];
    __nv_bfloat16* Gh = g_Gh + (size_t)b * C * C;
    __nv_bfloat16* Gl = g_Gl + (size_t)b * C * C;
    int e4 = seg * 1024 + threadIdx.x * 4;
    float4 s = make_float4(0.f, 0.f, 0.f, 0.f);
    #pragma unroll 8
    for (int ch = 0; ch < GC; ch++) {
        float4 v = *reinterpret_cast<const float4*>(
            &g_Gpart[((size_t)((b * GC + ch) * 6 + tile)) * 4096 + e4]);
        s.x += v.x; s.y += v.y; s.z += v.z; s.w += v.w;
    }
    float vs[4] = {s.x, s.y, s.z, s.w};
    #pragma unroll
    for (int u = 0; u < 4; u++) {
        int e = e4 + u;
        __nv_bfloat16 h = __float2bfloat16_rn(vs[u]);
        __nv_bfloat16 l = __float2bfloat16_rn(vs[u] - __bfloat162float(h));
        int m = e >> 6, n = e & 63;
        Gh[(i0 + m) * C + j0 + n] = h;
        Gl[(i0 + m) * C + j0 + n] = l;
        Gh[(j0 + n) * C + i0 + m] = h;
        Gl[(j0 + n) * C + i0 + m] = l;
    }
}

// ============ K2: fused (Wq@G)->T->sim partial, mma. grid (3 dc, NH, BATCH) ============
#define QPAD 200
#define TPAD 72
#define Q_WQ_H 0
#define Q_WQ_L (64 * QPAD)
#define Q_G_H  (2 * 64 * QPAD)
#define Q_G_L  (3 * 64 * QPAD)
#define Q_WK_H (4 * 64 * QPAD)
#define Q_WK_L (Q_WK_H + 64 * TPAD)
#define Q_T_H  (Q_WK_H + 2 * 64 * TPAD)
#define Q_T_L  (Q_WK_H + 3 * 64 * TPAD)
#define QG_SMEM ((4 * 64 * QPAD + 4 * 64 * TPAD) * 2)

__global__ void __launch_bounds__(256, 1) k_qgsim() {
    extern __shared__ __nv_bfloat16 sb[];
    int dc = blockIdx.x, n = blockIdx.y, b = blockIdx.z;
    int tid = threadIdx.x;
    int w    = tid >> 5, lane = tid & 31;
    int grp  = lane >> 2, tig = lane & 3;
    int wm   = w & 1, wn = w >> 1;
    int rsel = lane & 15, csel = (lane >> 4) << 3;

    int lrow = tid >> 2, lc = tid & 3;

    // group 1: Wq + G (phase 1 inputs)
    {
        const __nv_bfloat16* wqh = g_Wh + (size_t)(n * 64 + lrow) * C + lc * 48;
        const __nv_bfloat16* wql = g_Wl + (size_t)(n * 64 + lrow) * C + lc * 48;
        const __nv_bfloat16* gh  = g_Gh + (size_t)b * C * C + (size_t)(dc * 64 + lrow) * C + lc * 48;
        const __nv_bfloat16* gl  = g_Gl + (size_t)b * C * C + (size_t)(dc * 64 + lrow) * C + lc * 48;
        uint32_t dq_h = s2u(&sb[Q_WQ_H + lrow * QPAD + lc * 48]);
        uint32_t dq_l = s2u(&sb[Q_WQ_L + lrow * QPAD + lc * 48]);
        uint32_t dg_h = s2u(&sb[Q_G_H + lrow * QPAD + lc * 48]);
        uint32_t dg_l = s2u(&sb[Q_G_L + lrow * QPAD + lc * 48]);
        #pragma unroll
        for (int j = 0; j < 6; j++) {
            cp16(dq_h + j * 16, wqh + j * 8);
            cp16(dq_l + j * 16, wql + j * 8);
            cp16(dg_h + j * 16, gh + j * 8);
            cp16(dg_l + j * 16, gl + j * 8);
        }
        CP_COMMIT();
    }
    // group 2: Wk (phase 2 input; hidden behind phase-1 mma)
    {
        const __nv_bfloat16* wkh = g_Wh + WSZ + (size_t)(n * 64 + lrow) * C + dc * 64 + lc * 16;
        const __nv_bfloat16* wkl = g_Wl + WSZ + (size_t)(n * 64 + lrow) * C + dc * 64 + lc * 16;
        uint32_t dk_h = s2u(&sb[Q_WK_H + lrow * TPAD + lc * 16]);
        uint32_t dk_l = s2u(&sb[Q_WK_L + lrow * TPAD + lc * 16]);
        #pragma unroll
        for (int j = 0; j < 2; j++) {
            cp16(dk_h + j * 16, wkh + j * 8);
            cp16(dk_l + j * 16, wkl + j * 8);
        }
        CP_COMMIT();
    }
    CP_WAIT1();
    __syncthreads();

    uint32_t base = s2u(sb);
    float acc[2][2][4] = {};
    #pragma unroll
    for (int ks = 0; ks < 12; ks++) {
        int kb = ks * 16;
        uint32_t a[2][2][4];
        #pragma unroll
        for (int h = 0; h < 2; h++)
            #pragma unroll
            for (int mf = 0; mf < 2; mf++) {
                uint32_t addr = base + 2 * ((h ? Q_WQ_L : Q_WQ_H) + (wm * 32 + mf * 16 + rsel) * QPAD + kb + csel);
                LDSM4(a[h][mf][0], a[h][mf][1], a[h][mf][2], a[h][mf][3], addr);
            }
        uint32_t bm[2][4];
        #pragma unroll
        for (int h = 0; h < 2; h++) {
            uint32_t addr = base + 2 * ((h ? Q_G_L : Q_G_H) + (wn * 16 + rsel) * QPAD + kb + csel);
            LDSM4(bm[h][0], bm[h][1], bm[h][2], bm[h][3], addr);
        }
        #pragma unroll
        for (int mf = 0; mf < 2; mf++)
            #pragma unroll
            for (int nf = 0; nf < 2; nf++) {
                mma2(acc[mf][nf], a[0][mf][0], a[0][mf][1], a[0][mf][2], a[0][mf][3], bm[0][nf], bm[0][nf + 2]);
                mma2(acc[mf][nf], a[0][mf][0], a[0][mf][1], a[0][mf][2], a[0][mf][3], bm[1][nf], bm[1][nf + 2]);
                mma2(acc[mf][nf], a[1][mf][0], a[1][mf][1], a[1][mf][2], a[1][mf][3], bm[0][nf], bm[0][nf + 2]);
            }
    }

    #pragma unroll
    for (int mf = 0; mf < 2; mf++)
        #pragma unroll
        for (int nf = 0; nf < 2; nf++) {
            int row = wm * 32 + mf * 16 + grp;
            int col = wn * 16 + nf * 8 + tig * 2;
            uint32_t hi, lo;
            split_pack(acc[mf][nf][0], acc[mf][nf][1], hi, lo);
            *reinterpret_cast<uint32_t*>(&sb[Q_T_H + row * TPAD + col]) = hi;
            *reinterpret_cast<uint32_t*>(&sb[Q_T_L + row * TPAD + col]) = lo;
            split_pack(acc[mf][nf][2], acc[mf][nf][3], hi, lo);
            *reinterpret_cast<uint32_t*>(&sb[Q_T_H + (row + 8) * TPAD + col]) = hi;
            *reinterpret_cast<uint32_t*>(&sb[Q_T_L + (row + 8) * TPAD + col]) = lo;
        }
    CP_WAIT0();
    __syncthreads();

    float sacc[2][2][4] = {};
    #pragma unroll
    for (int ks = 0; ks < 4; ks++) {
        int kb = ks * 16;
        uint32_t a[2][2][4];
        #pragma unroll
        for (int h = 0; h < 2; h++)
            #pragma unroll
            for (int mf = 0; mf < 2; mf++) {
                uint32_t addr = base + 2 * ((h ? Q_T_L : Q_T_H) + (wm * 32 + mf * 16 + rsel) * TPAD + kb + csel);
                LDSM4(a[h][mf][0], a[h][mf][1], a[h][mf][2], a[h][mf][3], addr);
            }
        uint32_t bm[2][4];
        #pragma unroll
        for (int h = 0; h < 2; h++) {
            uint32_t addr = base + 2 * ((h ? Q_WK_L : Q_WK_H) + (wn * 16 + rsel) * TPAD + kb + csel);
            LDSM4(bm[h][0], bm[h][1], bm[h][2], bm[h][3], addr);
        }
        #pragma unroll
        for (int mf = 0; mf < 2; mf++)
            #pragma unroll
            for (int nf = 0; nf < 2; nf++) {
                mma2(sacc[mf][nf], a[0][mf][0], a[0][mf][1], a[0][mf][2], a[0][mf][3], bm[0][nf], bm[0][nf + 2]);
                mma2(sacc[mf][nf], a[0][mf][0], a[0][mf][1], a[0][mf][2], a[0][mf][3], bm[1][nf], bm[1][nf + 2]);
                mma2(sacc[mf][nf], a[1][mf][0], a[1][mf][1], a[1][mf][2], a[1][mf][3], bm[0][nf], bm[0][nf + 2]);
            }
    }

    float* sp = g_simp + (((size_t)(b * NH + n)) * 3 + dc) * 4096;
    #pragma unroll
    for (int mf = 0; mf < 2; mf++)
        #pragma unroll
        for (int nf = 0; nf < 2; nf++) {
            int row = wm * 32 + mf * 16 + grp;
            int col = wn * 16 + nf * 8 + tig * 2;
            *reinterpret_cast<float2*>(&sp[row * 64 + col])       = make_float2(sacc[mf][nf][0], sacc[mf][nf][1]);
            *reinterpret_cast<float2*>(&sp[(row + 8) * 64 + col]) = make_float2(sacc[mf][nf][2], sacc[mf][nf][3]);
        }
}

// ============ K3: fused softmax + AV (mma). grid (3 c-tiles, NH, BATCH) ============
#define AV_P_F    (3 * 64 * 68)
#define AV_BF_OFF ((AV_P_F + 64 * 65) * 4)
#define AV_A_H 0
#define AV_A_L (64 * TPAD)
#define AV_V_H (2 * 64 * TPAD)
#define AV_V_L (3 * 64 * TPAD)
#define AV_SMEM (AV_BF_OFF + 4 * 64 * TPAD * 2)

__global__ void __launch_bounds__(256, 1) k_av2() {
    extern __shared__ float sf[];
    float* sP   = sf;
    float* sims = sf + AV_P_F;
    __nv_bfloat16* sbm = reinterpret_cast<__nv_bfloat16*>(reinterpret_cast<char*>(sf) + AV_BF_OFF);

    int c0 = blockIdx.x * 64;
    int n  = blockIdx.y;
    int b  = blockIdx.z;

    int tid = threadIdx.x;
    int w    = tid >> 5, lane = tid & 31;
    int grp  = lane >> 2, tig = lane & 3;
    int wm   = w & 1, wn = w >> 1;
    int rsel = lane & 15, csel = (lane >> 4) << 3;

    int lrow = tid >> 2, lc = tid & 3;

    const float* p = g_simp + ((size_t)(b * NH + n)) * 3 * 4096;
    #pragma unroll
    for (int pp = 0; pp < 3; pp++) {
        const float* gp = p + pp * 4096 + lrow * 64 + lc * 16;
        uint32_t spu = s2u(&sP[pp * 64 * 68 + lrow * 68 + lc * 16]);
        #pragma unroll
        for (int j = 0; j < 4; j++)
            cp16(spu + j * 16, gp + j * 4);
    }
    {
        const __nv_bfloat16* gvh = g_Wh + 2 * WSZ + (size_t)(n * 64 + lrow) * C + c0 + lc * 16;
        const __nv_bfloat16* gvl = g_Wl + 2 * WSZ + (size_t)(n * 64 + lrow) * C + c0 + lc * 16;
        uint32_t dvh = s2u(&sbm[AV_V_H + lrow * TPAD + lc * 16]);
        uint32_t dvl = s2u(&sbm[AV_V_L + lrow * TPAD + lc * 16]);
        #pragma unroll
        for (int j = 0; j < 2; j++) {
            cp16(dvh + j * 16, gvh + j * 8);
            cp16(dvl + j * 16, gvl + j * 8);
        }
    }
    CP_COMMIT();
    CP_WAIT0();
    __syncthreads();

    for (int e = tid; e < 4096; e += 256) {
        int r = e >> 6, q = e & 63;
        sims[r * 65 + q] = (sP[r * 68 + q] + sP[64 * 68 + r * 68 + q] + sP[2 * 64 * 68 + r * 68 + q]) * ATT_SCALE;
    }
    __syncthreads();

    for (int r = w; r < 64; r += 8) {
        float v0 = sims[r * 65 + lane], v1 = sims[r * 65 + lane + 32];
        float m = fmaxf(v0, v1);
        #pragma unroll
        for (int off = 16; off; off >>= 1)
            m = fmaxf(m, __shfl_xor_sync(0xffffffffu, m, off));
        float e0 = __expf(v0 - m);
        float e1 = __expf(v1 - m);
        float sum = e0 + e1;
        #pragma unroll
        for (int off = 16; off; off >>= 1)
            sum += __shfl_xor_sync(0xffffffffu, sum, off);
        float inv = 1.f / sum;
        sims[r * 65 + lane]      = e0 * inv;
        sims[r * 65 + lane + 32] = e1 * inv;
    }
    __syncthreads();

    {
        int row = tid >> 2, q0 = (tid & 3) * 16;
        #pragma unroll
        for (int j2 = 0; j2 < 8; j2++) {
            uint32_t hi, lo;
            split_pack(sims[row * 65 + q0 + 2 * j2], sims[row * 65 + q0 + 2 * j2 + 1], hi, lo);
            *reinterpret_cast<uint32_t*>(&sbm[AV_A_H + row * TPAD + q0 + 2 * j2]) = hi;
            *reinterpret_cast<uint32_t*>(&sbm[AV_A_L + row * TPAD + q0 + 2 * j2]) = lo;
        }
    }
    __syncthreads();

    uint32_t base = s2u(sbm);
    float acc[2][2][4] = {};
    #pragma unroll
    for (int ks = 0; ks < 4; ks++) {
        int kb = ks * 16;
        uint32_t a[2][2][4];
        #pragma unroll
        for (int h = 0; h < 2; h++)
            #pragma unroll
            for (int mf = 0; mf < 2; mf++) {
                uint32_t addr = base + 2 * ((h ? AV_A_L : AV_A_H) + (wm * 32 + mf * 16 + rsel) * TPAD + kb + csel);
                LDSM4(a[h][mf][0], a[h][mf][1], a[h][mf][2], a[h][mf][3], addr);
            }
        uint32_t bm[2][2][2];
        #pragma unroll
        for (int h = 0; h < 2; h++) {
            uint32_t addr = base + 2 * ((h ? AV_V_L : AV_V_H) + (kb + rsel) * TPAD + wn * 16 + csel);
            uint32_t r0, r1, r2, r3;
            LDSM4T(r0, r1, r2, r3, addr);
            bm[h][0][0] = r0; bm[h][0][1] = r1;
            bm[h][1][0] = r2; bm[h][1][1] = r3;
        }
        #pragma unroll
        for (int mf = 0; mf < 2; mf++)
            #pragma unroll
            for (int nf = 0; nf < 2; nf++) {
                mma2(acc[mf][nf], a[0][mf][0], a[0][mf][1], a[0][mf][2], a[0][mf][3], bm[0][nf][0], bm[0][nf][1]);
                mma2(acc[mf][nf], a[0][mf][0], a[0][mf][1], a[0][mf][2], a[0][mf][3], bm[1][nf][0], bm[1][nf][1]);
                mma2(acc[mf][nf], a[1][mf][0], a[1][mf][1], a[1][mf][2], a[1][mf][3], bm[0][nf][0], bm[0][nf][1]);
            }
    }

    #pragma unroll
    for (int mf = 0; mf < 2; mf++)
        #pragma unroll
        for (int nf = 0; nf < 2; nf++) {
            int row = wm * 32 + mf * 16 + grp;
            int col = c0 + wn * 16 + nf * 8 + tig * 2;
            size_t base0 = ((size_t)b * INNER + n * 64 + row) * C + col;
            size_t base8 = ((size_t)b * INNER + n * 64 + row + 8) * C + col;
            uint32_t hi, lo;
            split_pack(acc[mf][nf][0], acc[mf][nf][1], hi, lo);
            *reinterpret_cast<uint32_t*>(&g_AVh[base0]) = hi;
            *reinterpret_cast<uint32_t*>(&g_AVl[base0]) = lo;
            split_pack(acc[mf][nf][2], acc[mf][nf][3], hi, lo);
            *reinterpret_cast<uint32_t*>(&g_AVh[base8]) = hi;
            *reinterpret_cast<uint32_t*>(&g_AVl[base8]) = lo;
        }
}

// ============ K4: Mpart = Wo @ AV (mma, split-K 4). grid (3, 12, BATCH) ============
#define WOPAD 136
#define M_WO_H 0
#define M_WO_L (64 * WOPAD)
#define M_AV_H (2 * 64 * WOPAD)
#define M_AV_L (M_AV_H + 128 * TPAD)
#define M_SMEM ((2 * 64 * WOPAD + 2 * 128 * TPAD) * 2)

__global__ void __launch_bounds__(256, 2) k_m() {
    extern __shared__ __nv_bfloat16 sb[];
    int c0 = blockIdx.x * 64;
    int o0 = (blockIdx.y % 3) * 64;
    int kc = blockIdx.y / 3;
    int b  = blockIdx.z;
    int k0 = kc * 128;

    int tid = threadIdx.x;
    int w    = tid >> 5, lane = tid & 31;
    int grp  = lane >> 2, tig = lane & 3;
    int wm   = w & 1, wn = w >> 1;
    int rsel = lane & 15, csel = (lane >> 4) << 3;

    {
        int lrow = tid >> 2, lc = (tid & 3) * 32;
        const __nv_bfloat16* gwh = g_Wh + 3 * WSZ + (size_t)(o0 + lrow) * INNER + k0 + lc;
        const __nv_bfloat16* gwl = g_Wl + 3 * WSZ + (size_t)(o0 + lrow) * INNER + k0 + lc;
        uint32_t dwh = s2u(&sb[M_WO_H + lrow * WOPAD + lc]);
        uint32_t dwl = s2u(&sb[M_WO_L + lrow * WOPAD + lc]);
        #pragma unroll
        for (int j = 0; j < 4; j++) {
            cp16(dwh + j * 16, gwh + j * 8);
            cp16(dwl + j * 16, gwl + j * 8);
        }
        int arow = tid >> 1, ac = (tid & 1) * 32;
        const __nv_bfloat16* gah = g_AVh + ((size_t)b * INNER + k0 + arow) * C + c0 + ac;
        const __nv_bfloat16* gal = g_AVl + ((size_t)b * INNER + k0 + arow) * C + c0 + ac;
        uint32_t dah = s2u(&sb[M_AV_H + arow * TPAD + ac]);
        uint32_t dal = s2u(&sb[M_AV_L + arow * TPAD + ac]);
        #pragma unroll
        for (int j = 0; j < 4; j++) {
            cp16(dah + j * 16, gah + j * 8);
            cp16(dal + j * 16, gal + j * 8);
        }
        CP_COMMIT();
        CP_WAIT0();
    }
    __syncthreads();

    uint32_t base = s2u(sb);
    float acc[2][2][4] = {};
    #pragma unroll
    for (int ks = 0; ks < 8; ks++) {
        int kb = ks * 16;
        uint32_t a[2][2][4];
        #pragma unroll
        for (int h = 0; h < 2; h++)
            #pragma unroll
            for (int mf = 0; mf < 2; mf++) {
                uint32_t addr = base + 2 * ((h ? M_WO_L : M_WO_H) + (wm * 32 + mf * 16 + rsel) * WOPAD + kb + csel);
                LDSM4(a[h][mf][0], a[h][mf][1], a[h][mf][2], a[h][mf][3], addr);
            }
        uint32_t bm[2][2][2];
        #pragma unroll
        for (int h = 0; h < 2; h++) {
            uint32_t addr = base + 2 * ((h ? M_AV_L : M_AV_H) + (kb + rsel) * TPAD + wn * 16 + csel);
            uint32_t r0, r1, r2, r3;
            LDSM4T(r0, r1, r2, r3, addr);
            bm[h][0][0] = r0; bm[h][0][1] = r1;
            bm[h][1][0] = r2; bm[h][1][1] = r3;
        }
        #pragma unroll
        for (int mf = 0; mf < 2; mf++)
            #pragma unroll
            for (int nf = 0; nf < 2; nf++) {
                mma2(acc[mf][nf], a[0][mf][0], a[0][mf][1], a[0][mf][2], a[0][mf][3], bm[0][nf][0], bm[0][nf][1]);
                mma2(acc[mf][nf], a[0][mf][0], a[0][mf][1], a[0][mf][2], a[0][mf][3], bm[1][nf][0], bm[1][nf][1]);
                mma2(acc[mf][nf], a[1][mf][0], a[1][mf][1], a[1][mf][2], a[1][mf][3], bm[0][nf][0], bm[0][nf][1]);
            }
    }

    float* Mp = g_Mpart + ((size_t)(b * 4 + kc)) * C * C;
    #pragma unroll
    for (int mf = 0; mf < 2; mf++)
        #pragma unroll
        for (int nf = 0; nf < 2; nf++) {
            int row = o0 + wm * 32 + mf * 16 + grp;
            int col = c0 + wn * 16 + nf * 8 + tig * 2;
            *reinterpret_cast<float2*>(&Mp[row * C + col])       = make_float2(acc[mf][nf][0], acc[mf][nf][1]);
            *reinterpret_cast<float2*>(&Mp[(row + 8) * C + col]) = make_float2(acc[mf][nf][2], acc[mf][nf][3]);
        }
}

// float4 reduce: grid (36, BATCH)
__global__ void k_m_reduce() {
    int b = blockIdx.y;
    int e4 = (blockIdx.x * 256 + threadIdx.x) * 4;
    if (e4 < C * C) {
        float4 s = make_float4(0.f, 0.f, 0.f, 0.f);
        #pragma unroll
        for (int kc = 0; kc < 4; kc++) {
            float4 v = *reinterpret_cast<const float4*>(
                &g_Mpart[((size_t)(b * 4 + kc)) * C * C + e4]);
            s.x += v.x; s.y += v.y; s.z += v.z; s.w += v.w;
        }
        uint32_t h0, l0, h1, l1;
        split_pack(s.x, s.y, h0, l0);
        split_pack(s.z, s.w, h1, l1);
        *reinterpret_cast<uint2*>(&g_Mh[(size_t)b * C * C + e4]) = make_uint2(h0, h1);
        *reinterpret_cast<uint2*>(&g_Ml[(size_t)b * C * C + e4]) = make_uint2(l0, l1);
    }
}

// ============ K5: out = M @ X + bo (cp.async 3-stage + ldmatrix) ============
#define MPAD 40
#define SPAD 136
#define O_M_BYTES     (2 * 64 * MPAD * 2)
#define O_X_BYTES     (2 * 32 * SPAD * 2)
#define O_M_SPLIT_OFF (64 * MPAD)
#define O_X_SPLIT_OFF (32 * SPAD)
#define O_STAGE       (O_M_BYTES + O_X_BYTES)
#define O_SMEM        (3 * O_STAGE)
#define O_ITERS       6

__global__ void __launch_bounds__(256, 2) k_out(const float* __restrict__ bo,
                                                float* __restrict__ out) {
    extern __shared__ char dyn[];
    int o0    = blockIdx.x * 64;
    int s0blk = blockIdx.y * 128;
    int b     = blockIdx.z;

    int tid  = threadIdx.x;
    int w    = tid >> 5, lane = tid & 31;
    int grp  = lane >> 2, tig = lane & 3;
    int wm   = w & 1, wn = w >> 1;
    int rsel = lane & 15, csel = (lane >> 4) << 3;

    const __nv_bfloat16* xh = g_Xh + (size_t)b * C * S;
    const __nv_bfloat16* xl = g_Xl + (size_t)b * C * S;
    const __nv_bfloat16* mh = g_Mh + (size_t)b * C * C;
    const __nv_bfloat16* ml = g_Ml + (size_t)b * C * C;

    float acc[2][4][4] = {};

    int mrow = tid >> 2, mk8 = (tid & 3) * 8;
    int krow = tid >> 3, s16o = (tid & 7) * 16;

    auto issue = [&](int st, int kc) {
        uint32_t mb  = s2u(dyn + st * O_STAGE);
        uint32_t xbs = mb + O_M_BYTES;
        const __nv_bfloat16* gmh = mh + (o0 + mrow) * C + kc + mk8;
        const __nv_bfloat16* gml = ml + (o0 + mrow) * C + kc + mk8;
        uint32_t sm = mb + 2 * (mrow * MPAD + mk8);
        cp16(sm, gmh);
        cp16(sm + 2 * O_M_SPLIT_OFF, gml);
        const __nv_bfloat16* gxh = xh + (size_t)(kc + krow) * S + s0blk + s16o;
        const __nv_bfloat16* gxl = xl + (size_t)(kc + krow) * S + s0blk + s16o;
        uint32_t sx = xbs + 2 * (krow * SPAD + s16o);
        cp16(sx, gxh);
        cp16(sx + 16, gxh + 8);
        cp16(sx + 2 * O_X_SPLIT_OFF, gxl);
        cp16(sx + 2 * O_X_SPLIT_OFF + 16, gxl + 8);
        CP_COMMIT();
    };

    issue(0, 0);
    issue(1, 32);

    for (int it = 0; it < O_ITERS; it++) {
        if (it + 1 < O_ITERS) { CP_WAIT1(); } else { CP_WAIT0(); }
        __syncthreads();   // single barrier per iter

        if (it + 2 < O_ITERS) issue((it + 2) % 3, (it + 2) * 32);

        uint32_t sMu = s2u(dyn + (it % 3) * O_STAGE);
        uint32_t sXu = sMu + O_M_BYTES;
        #pragma unroll
        for (int ks = 0; ks < 2; ks++) {
            int kb = ks * 16;
            uint32_t a[2][2][4];
            #pragma unroll
            for (int h = 0; h < 2; h++)
                #pragma unroll
                for (int mf = 0; mf < 2; mf++) {
                    uint32_t addr = sMu + 2 * (h * O_M_SPLIT_OFF + (wm * 32 + mf * 16 + rsel) * MPAD + kb + csel);
                    LDSM4(a[h][mf][0], a[h][mf][1], a[h][mf][2], a[h][mf][3], addr);
                }
            uint32_t bb[2][4][2];
            #pragma unroll
            for (int h = 0; h < 2; h++)
                #pragma unroll
                for (int nfp = 0; nfp < 2; nfp++) {
                    int scol = wn * 32 + nfp * 16;
                    uint32_t addr = sXu + 2 * (h * O_X_SPLIT_OFF + (kb + rsel) * SPAD + scol + csel);
                    uint32_t r0, r1, r2, r3;
                    LDSM4T(r0, r1, r2, r3, addr);
                    bb[h][nfp * 2][0] = r0; bb[h][nfp * 2][1] = r1;
                    bb[h][nfp * 2 + 1][0] = r2; bb[h][nfp * 2 + 1][1] = r3;
                }
            #pragma unroll
            for (int mf = 0; mf < 2; mf++)
                #pragma unroll
                for (int nf = 0; nf < 4; nf++) {
                    mma2(acc[mf][nf], a[0][mf][0], a[0][mf][1], a[0][mf][2], a[0][mf][3], bb[0][nf][0], bb[0][nf][1]);
                    mma2(acc[mf][nf], a[0][mf][0], a[0][mf][1], a[0][mf][2], a[0][mf][3], bb[1][nf][0], bb[1][nf][1]);
                    mma2(acc[mf][nf], a[1][mf][0], a[1][mf][1], a[1][mf][2], a[1][mf][3], bb[0][nf][0], bb[0][nf][1]);
                }
        }
    }

    #pragma unroll
    for (int mf = 0; mf < 2; mf++) {
        int row0 = o0 + wm * 32 + mf * 16 + grp;
        float bias0 = bo[row0];
        float bias1 = bo[row0 + 8];
        #pragma unroll
        for (int nf = 0; nf < 4; nf++) {
            int col = s0blk + wn * 32 + nf * 8 + tig * 2;
            *reinterpret_cast<float2*>(&out[((size_t)b * C + row0) * S + col]) =
                make_float2(acc[mf][nf][0] + bias0, acc[mf][nf][1] + bias0);
            *reinterpret_cast<float2*>(&out[((size_t)b * C + row0 + 8) * S + col]) =
                make_float2(acc[mf][nf][2] + bias1, acc[mf][nf][3] + bias1);
        }
    }
}

// ---------------- launch ----------------
extern "C" void kernel_launch(void* const* d_in, const int* in_sizes, int n_in,
                              void* d_out, int out_size) {
    const float* x  = (const float*)d_in[0];
    const float* wq = (const float*)d_in[1];
    const float* wk = (const float*)d_in[2];
    const float* wv = (const float*)d_in[3];
    const float* wo = (const float*)d_in[4];
    const float* bo = (const float*)d_in[5];
    float* out = (float*)d_out;

    cudaFuncSetAttribute(k_gram,  cudaFuncAttributeMaxDynamicSharedMemorySize, G_SMEM);
    cudaFuncSetAttribute(k_qgsim, cudaFuncAttributeMaxDynamicSharedMemorySize, QG_SMEM);
    cudaFuncSetAttribute(k_av2,   cudaFuncAttributeMaxDynamicSharedMemorySize, AV_SMEM);
    cudaFuncSetAttribute(k_m,     cudaFuncAttributeMaxDynamicSharedMemorySize, M_SMEM);
    cudaFuncSetAttribute(k_out,   cudaFuncAttributeMaxDynamicSharedMemorySize, O_SMEM);

    int cvt_blocks = (int)((XTOT + 4 * WSZ) / (256 * 8));
    k_cvt<<<cvt_blocks, 256>>>(x, wq, wk, wv, wo);
    k_gram<<<dim3(6, GC, BATCH), 256, G_SMEM>>>();
    k_gram_reduce<<<dim3(6, 4, BATCH), 256>>>();
    k_qgsim<<<dim3(3, NH, BATCH), 256, QG_SMEM>>>();
    k_av2<<<dim3(3, NH, BATCH), 256, AV_SMEM>>>();
    k_m<<<dim3(3, 12, BATCH), 256, M_SMEM>>>();
    k_m_reduce<<<dim3(36, BATCH), 256>>>();
    k_out<<<dim3(3, S / 128, BATCH), 256, O_SMEM>>>(bo, out);
}